// round 16
// baseline (speedup 1.0000x reference)
#include <cuda_runtime.h>
#include <cuda_fp16.h>
#include <cstdint>

// Fused SelfAttention, tensor-core HMMA (mma.sync f16, fp32 accum), 1-term fp16.
// E=128, S=32, H=4, D=32. CTA = 128 rows (4 batches), 256 threads, grid 4096.
// Warp w: m0 = (w>>1)*32 (batch), n0 = (w&1)*64 (head pair 2*(w&1)).
// Warp tile 32x64 (acc[2][8][4]); attention register-resident per head.
// fillW via cp.async.cg (overlaps softmax/ctx). Separate CTX smem buffer.
//
// SMEM:
//   A   @0     : fp16 [128][128], 256B rows, 16B-chunk xor swizzle. 32KB
//   W   @32768 : fp16 [128][128] swizzled weight image.             32KB
//   CTX @65536 : fp16 [128][128] like A.                            32KB
//   LN partials @98304 : float2[128][2].                             2KB

typedef unsigned int u32;

#define NT 256
#define AOFF 0
#define WOFF 32768
#define CTXOFF 65536
#define POFF 98304
#define SMEM_BYTES 100352
#define QSCALE 0.17677669529663687f

// 4 weights x 32KB swizzled fp16 image
__device__ __align__(16) unsigned char g_Wpk[131072];

// ---------------- prep: W -> fp16 swizzled smem images ----------------
__global__ void prep_split(const float* __restrict__ Wq, const float* __restrict__ Wk,
                           const float* __restrict__ Wv, const float* __restrict__ Wo) {
    int id = blockIdx.x * blockDim.x + threadIdx.x;   // 0..32767 u32 words
    const float* W = (id < 8192) ? Wq : (id < 16384) ? Wk : (id < 24576) ? Wv : Wo;
    int rem = id & 8191;
    int f = rem >> 6;          // row 0..127 (64 u32 words per 256B row)
    int w = rem & 63;
    int pc = w >> 2, j = w & 3;
    int lc = pc ^ (f & 7);
    int k0 = lc * 8 + j * 2;
    __half2 p = __halves2half2(__float2half_rn(W[f * 128 + k0]),
                               __float2half_rn(W[f * 128 + k0 + 1]));
    ((u32*)g_Wpk)[id] = *(u32*)&p;
}

// ---------------- helpers ----------------
__device__ __forceinline__ u32 s2u(const void* p) {
    u32 a;
    asm("{ .reg .u64 t; cvta.to.shared.u64 t, %1; cvt.u32.u64 %0, t; }" : "=r"(a) : "l"(p));
    return a;
}
__device__ __forceinline__ void ldsm4(u32* r, u32 a) {
    asm volatile("ldmatrix.sync.aligned.m8n8.x4.shared.b16 {%0,%1,%2,%3}, [%4];"
                 : "=r"(r[0]), "=r"(r[1]), "=r"(r[2]), "=r"(r[3]) : "r"(a));
}
__device__ __forceinline__ u32 movm_t(u32 s) {
    u32 d;
    asm("movmatrix.sync.aligned.m8n8.trans.b16 %0, %1;" : "=r"(d) : "r"(s));
    return d;
}
__device__ __forceinline__ void mma16816(float* c, const u32* a, u32 b0, u32 b1) {
    asm volatile(
        "mma.sync.aligned.m16n8k16.row.col.f32.f16.f16.f32 "
        "{%0,%1,%2,%3}, {%4,%5,%6,%7}, {%8,%9}, {%0,%1,%2,%3};"
        : "+f"(c[0]), "+f"(c[1]), "+f"(c[2]), "+f"(c[3])
        : "r"(a[0]), "r"(a[1]), "r"(a[2]), "r"(a[3]), "r"(b0), "r"(b1));
}
__device__ __forceinline__ u32 pkhf(float a, float b) {
    __half2 t = __halves2half2(__float2half_rn(a), __float2half_rn(b));
    return *(u32*)&t;
}
__device__ __forceinline__ void cpa16(u32 dst, const void* src) {
    asm volatile("cp.async.cg.shared.global [%0], [%1], 16;" :: "r"(dst), "l"(src));
}
__device__ __forceinline__ void cpa_commit() {
    asm volatile("cp.async.commit_group;" ::: "memory");
}
__device__ __forceinline__ void cpa_wait0() {
    asm volatile("cp.async.wait_group 0;" ::: "memory");
}

// issue async copy of weight image g into W buffer (no wait)
__device__ __forceinline__ void fillW_async(u32 smW, int g, int tid) {
    const char* src = (const char*)g_Wpk + g * 32768;
#pragma unroll
    for (int p = 0; p < 8; ++p) {
        int off = (p * NT + tid) * 16;
        cpa16(smW + off, src + off);
    }
    cpa_commit();
}

// C[m0:+32][n0:+64] = A(128x128 fp16) @ W^T(128x128 fp16), 1-term.
__device__ __forceinline__ void gemm64(u32 smA, u32 smW, int m0, int n0, int lane,
                                       float acc[2][8][4]) {
    u32 aRow[2]; int asw[2];
#pragma unroll
    for (int mt = 0; mt < 2; ++mt) {
        int ar = m0 + mt * 16 + (lane & 7) + ((lane & 8) ? 8 : 0);
        aRow[mt] = smA + ar * 256; asw[mt] = ar & 7;
    }
    const int acs = lane >> 4;
    u32 bRow[4]; int bsw[4];
#pragma unroll
    for (int ng = 0; ng < 4; ++ng) {
        int br = n0 + ng * 16 + (lane & 7) + ((lane & 16) ? 8 : 0);
        bRow[ng] = smW + br * 256; bsw[ng] = br & 7;
    }
    const int bcs = (lane >> 3) & 1;
#pragma unroll
    for (int mt = 0; mt < 2; ++mt)
#pragma unroll
        for (int nf = 0; nf < 8; ++nf)
#pragma unroll
            for (int c = 0; c < 4; ++c) acc[mt][nf][c] = 0.f;

#pragma unroll
    for (int j = 0; j < 8; ++j) {
        const int ach = 2 * j + acs, bch = 2 * j + bcs;
        u32 ah[2][4], bh[4][4];
#pragma unroll
        for (int mt = 0; mt < 2; ++mt)
            ldsm4(ah[mt], aRow[mt] + ((ach ^ asw[mt]) << 4));
#pragma unroll
        for (int ng = 0; ng < 4; ++ng)
            ldsm4(bh[ng], bRow[ng] + ((bch ^ bsw[ng]) << 4));
#pragma unroll
        for (int mt = 0; mt < 2; ++mt)
#pragma unroll
            for (int ng = 0; ng < 4; ++ng) {
                mma16816(acc[mt][2 * ng],     ah[mt], bh[ng][0], bh[ng][1]);
                mma16816(acc[mt][2 * ng + 1], ah[mt], bh[ng][2], bh[ng][3]);
            }
    }
}

// 32x32 c-frags -> fp16 into an A-style [128][128] image at (m0, c0).
__device__ __forceinline__ void store_ctx32(char* dst, const float C[2][4][4],
                                            int m0, int c0, int lane) {
#pragma unroll
    for (int mt = 0; mt < 2; ++mt) {
        int r = m0 + mt * 16 + (lane >> 2);
        char* row0 = dst + r * 256;
        char* row1 = dst + (r + 8) * 256;
        int sw = r & 7;
#pragma unroll
        for (int nf = 0; nf < 4; ++nf) {
            int c = c0 + nf * 8 + 2 * (lane & 3);
            u32 h01 = pkhf(C[mt][nf][0], C[mt][nf][1]);
            u32 h23 = pkhf(C[mt][nf][2], C[mt][nf][3]);
            int ch = c >> 3, bo_ = (c & 7) * 2;
            *(u32*)(row0 + ((ch ^ sw) << 4) + bo_) = h01;
            *(u32*)(row1 + ((ch ^ sw) << 4) + bo_) = h23;
        }
    }
}

// ---------------- main kernel ----------------
__global__ void __launch_bounds__(NT, 2)
fused_attn_fa(const float* __restrict__ inputs,
              const float* __restrict__ bq, const float* __restrict__ bk,
              const float* __restrict__ bv, const float* __restrict__ bo,
              const float* __restrict__ gamma, const float* __restrict__ beta,
              float* __restrict__ outp)
{
    extern __shared__ char sm[];
    const int tid = threadIdx.x;
    const int lane = tid & 31;
    const int warp = tid >> 5;
    const u32 smb = s2u(sm);
    const u32 smA = smb + AOFF, smW = smb + WOFF, smCTX = smb + CTXOFF;
    const int m0 = (warp >> 1) * 32;    // batch block (rows): 0..96
    const int n0 = (warp & 1) * 64;     // head-pair block (cols): 0 or 64
    const int ng_id = warp & 1;
    const size_t tbase = (size_t)blockIdx.x * 16384;

    // ---- fill A (x -> fp16, 128 rows) + async Wq ----
    fillW_async(smW, 0, tid);
    {
        const float4* gx = (const float4*)(inputs + tbase);
#pragma unroll
        for (int p = 0; p < 16; ++p) {
            int e = p * NT + tid;
            int row = e >> 5, c4 = e & 31;
            float4 v = __ldg(gx + e);
            uint2 hi = make_uint2(pkhf(v.x, v.y), pkhf(v.z, v.w));
            char* arow = sm + AOFF + row * 256;
            int ch = c4 >> 1, off8 = (c4 & 1) * 8, sw = row & 7;
            *(uint2*)(arow + ((ch ^ sw) << 4) + off8) = hi;
        }
    }
    cpa_wait0();
    __syncthreads();

    float acc[2][8][4];

    // ======== Q gemm -> fp16 a-frags per head (bias+scale folded) ========
    gemm64(smA, smW, m0, n0, lane, acc);
    u32 qh[2][2][2][4];   // [head][ms][ks][4]
#pragma unroll
    for (int mt = 0; mt < 2; ++mt)
#pragma unroll
        for (int nf = 0; nf < 8; ++nf) {
            int c = n0 + nf * 8 + 2 * (lane & 3);
            float2 b2 = __ldg((const float2*)(bq + c));
            float q0 = (acc[mt][nf][0] + b2.x) * QSCALE;
            float q1 = (acc[mt][nf][1] + b2.y) * QSCALE;
            float q2 = (acc[mt][nf][2] + b2.x) * QSCALE;
            float q3 = (acc[mt][nf][3] + b2.y) * QSCALE;
            int hh = nf >> 2, ks = (nf >> 1) & 1, o = (nf & 1) * 2;
            qh[hh][mt][ks][o] = pkhf(q0, q1);
            qh[hh][mt][ks][o + 1] = pkhf(q2, q3);
        }
    __syncthreads();          // done reading Wq
    fillW_async(smW, 1, tid); // Wk (async)
    cpa_wait0();
    __syncthreads();

    // ======== K gemm -> score B-frags per head (+bk) ========
    gemm64(smA, smW, m0, n0, lane, acc);
    u32 kbh[2][2][2][4];  // [head][mk][tb][nf_local]
#pragma unroll
    for (int mt = 0; mt < 2; ++mt)
#pragma unroll
        for (int nf = 0; nf < 8; ++nf) {
            int c = n0 + nf * 8 + 2 * (lane & 3);
            float2 b2 = __ldg((const float2*)(bk + c));
            int hh = nf >> 2, nfl = nf & 3;
            kbh[hh][mt][0][nfl] = pkhf(acc[mt][nf][0] + b2.x, acc[mt][nf][1] + b2.y);
            kbh[hh][mt][1][nfl] = pkhf(acc[mt][nf][2] + b2.x, acc[mt][nf][3] + b2.y);
        }
    __syncthreads();          // done reading Wk
    fillW_async(smW, 2, tid); // Wv (async, overlaps scores/softmax)

    // ======== scores + softmax + P, per head (register-only) ========
    u32 ph[2][2][2][4];   // [head][mt][kt][4]
#pragma unroll
    for (int hh = 0; hh < 2; ++hh) {
        float S[2][4][4];
#pragma unroll
        for (int mt = 0; mt < 2; ++mt)
#pragma unroll
            for (int nf = 0; nf < 4; ++nf)
#pragma unroll
                for (int c = 0; c < 4; ++c) S[mt][nf][c] = 0.f;
#pragma unroll
        for (int ks = 0; ks < 2; ++ks)
#pragma unroll
            for (int ms = 0; ms < 2; ++ms)
#pragma unroll
                for (int mk = 0; mk < 2; ++mk)
#pragma unroll
                    for (int tb = 0; tb < 2; ++tb)
                        mma16816(S[ms][2 * mk + tb], qh[hh][ms][ks],
                                 kbh[hh][mk][tb][2 * ks], kbh[hh][mk][tb][2 * ks + 1]);
        float mx[2][2], iv[2][2];
#pragma unroll
        for (int mt = 0; mt < 2; ++mt)
#pragma unroll
            for (int hf = 0; hf < 2; ++hf) {
                float m = -1e30f;
#pragma unroll
                for (int nf = 0; nf < 4; ++nf)
                    m = fmaxf(m, fmaxf(S[mt][nf][hf * 2], S[mt][nf][hf * 2 + 1]));
                m = fmaxf(m, __shfl_xor_sync(~0u, m, 1));
                m = fmaxf(m, __shfl_xor_sync(~0u, m, 2));
                mx[mt][hf] = m;
            }
#pragma unroll
        for (int mt = 0; mt < 2; ++mt)
#pragma unroll
            for (int nf = 0; nf < 4; ++nf) {
                S[mt][nf][0] = __expf(S[mt][nf][0] - mx[mt][0]);
                S[mt][nf][1] = __expf(S[mt][nf][1] - mx[mt][0]);
                S[mt][nf][2] = __expf(S[mt][nf][2] - mx[mt][1]);
                S[mt][nf][3] = __expf(S[mt][nf][3] - mx[mt][1]);
            }
#pragma unroll
        for (int mt = 0; mt < 2; ++mt)
#pragma unroll
            for (int hf = 0; hf < 2; ++hf) {
                float s = 0.f;
#pragma unroll
                for (int nf = 0; nf < 4; ++nf)
                    s += S[mt][nf][hf * 2] + S[mt][nf][hf * 2 + 1];
                s += __shfl_xor_sync(~0u, s, 1);
                s += __shfl_xor_sync(~0u, s, 2);
                iv[mt][hf] = 1.f / s;
            }
#pragma unroll
        for (int mt = 0; mt < 2; ++mt)
#pragma unroll
            for (int nf = 0; nf < 4; ++nf) {
                float p0 = S[mt][nf][0] * iv[mt][0];
                float p1 = S[mt][nf][1] * iv[mt][0];
                float p2 = S[mt][nf][2] * iv[mt][1];
                float p3 = S[mt][nf][3] * iv[mt][1];
                int kt = nf >> 1, o = (nf & 1) * 2;
                ph[hh][mt][kt][o] = pkhf(p0, p1);
                ph[hh][mt][kt][o + 1] = pkhf(p2, p3);
            }
    }
    cpa_wait0();
    __syncthreads();          // Wv ready

    // ======== V gemm -> ctx B-frags per head (+bv, movmatrix) ========
    gemm64(smA, smW, m0, n0, lane, acc);
    u32 vbh[2][2][2][4];  // [head][kt][tb][nf_local]
#pragma unroll
    for (int mt = 0; mt < 2; ++mt)
#pragma unroll
        for (int nf = 0; nf < 8; ++nf) {
            int c = n0 + nf * 8 + 2 * (lane & 3);
            float2 b2 = __ldg((const float2*)(bv + c));
            u32 h01 = pkhf(acc[mt][nf][0] + b2.x, acc[mt][nf][1] + b2.y);
            u32 h23 = pkhf(acc[mt][nf][2] + b2.x, acc[mt][nf][3] + b2.y);
            int hh = nf >> 2, nfl = nf & 3;
            vbh[hh][mt][0][nfl] = movm_t(h01);
            vbh[hh][mt][1][nfl] = movm_t(h23);
        }
    __syncthreads();          // done reading Wv (A no longer needed)
    fillW_async(smW, 3, tid); // Wo (async, overlaps ctx)

    // ======== ctx per head -> CTX buffer ========
#pragma unroll
    for (int hh = 0; hh < 2; ++hh) {
        float C[2][4][4];
#pragma unroll
        for (int mt = 0; mt < 2; ++mt)
#pragma unroll
            for (int nf = 0; nf < 4; ++nf)
#pragma unroll
                for (int c = 0; c < 4; ++c) C[mt][nf][c] = 0.f;
#pragma unroll
        for (int kt = 0; kt < 2; ++kt)
#pragma unroll
            for (int ms = 0; ms < 2; ++ms)
#pragma unroll
                for (int nf = 0; nf < 4; ++nf)
                    mma16816(C[ms][nf], ph[hh][ms][kt],
                             vbh[hh][kt][0][nf], vbh[hh][kt][1][nf]);
        store_ctx32(sm + CTXOFF, C, m0, n0 + hh * 32, lane);
    }
    cpa_wait0();
    __syncthreads();          // Wo ready, CTX complete

    // ======== out projection (CTX @ Wo^T) + epilogue ========
    gemm64(smCTX, smW, m0, n0, lane, acc);

    {
        float s1[2][2] = {{0.f, 0.f}, {0.f, 0.f}};
        float s2[2][2] = {{0.f, 0.f}, {0.f, 0.f}};
#pragma unroll
        for (int mt = 0; mt < 2; ++mt) {
            int r = m0 + mt * 16 + (lane >> 2);
#pragma unroll
            for (int nf = 0; nf < 8; ++nf) {
                int c = n0 + nf * 8 + 2 * (lane & 3);
                float2 b2 = __ldg((const float2*)(bo + c));
                float2 xa = __ldg((const float2*)(inputs + tbase + (size_t)r * 128 + c));
                float2 xb = __ldg((const float2*)(inputs + tbase + (size_t)(r + 8) * 128 + c));
                acc[mt][nf][0] += b2.x + xa.x; acc[mt][nf][1] += b2.y + xa.y;
                acc[mt][nf][2] += b2.x + xb.x; acc[mt][nf][3] += b2.y + xb.y;
                s1[mt][0] += acc[mt][nf][0] + acc[mt][nf][1];
                s2[mt][0] += acc[mt][nf][0] * acc[mt][nf][0] + acc[mt][nf][1] * acc[mt][nf][1];
                s1[mt][1] += acc[mt][nf][2] + acc[mt][nf][3];
                s2[mt][1] += acc[mt][nf][2] * acc[mt][nf][2] + acc[mt][nf][3] * acc[mt][nf][3];
            }
        }
#pragma unroll
        for (int mt = 0; mt < 2; ++mt)
#pragma unroll
            for (int hf = 0; hf < 2; ++hf) {
                s1[mt][hf] += __shfl_xor_sync(~0u, s1[mt][hf], 1);
                s1[mt][hf] += __shfl_xor_sync(~0u, s1[mt][hf], 2);
                s2[mt][hf] += __shfl_xor_sync(~0u, s2[mt][hf], 1);
                s2[mt][hf] += __shfl_xor_sync(~0u, s2[mt][hf], 2);
            }
        float2* part = (float2*)(sm + POFF);
        if ((lane & 3) == 0) {
#pragma unroll
            for (int mt = 0; mt < 2; ++mt) {
                int r = m0 + mt * 16 + (lane >> 2);
                part[r * 2 + ng_id] = make_float2(s1[mt][0], s2[mt][0]);
                part[(r + 8) * 2 + ng_id] = make_float2(s1[mt][1], s2[mt][1]);
            }
        }
        __syncthreads();
        float mu[2][2], rs[2][2];
#pragma unroll
        for (int mt = 0; mt < 2; ++mt)
#pragma unroll
            for (int hf = 0; hf < 2; ++hf) {
                int r = m0 + mt * 16 + (lane >> 2) + hf * 8;
                float2 p0 = part[r * 2 + 0], p1 = part[r * 2 + 1];
                float S1 = p0.x + p1.x;
                float S2 = p0.y + p1.y;
                float m = S1 * (1.f / 128.f);
                float v = S2 * (1.f / 128.f) - m * m;
                mu[mt][hf] = m;
                rs[mt][hf] = rsqrtf(v + 1e-5f);
            }
#pragma unroll
        for (int mt = 0; mt < 2; ++mt) {
            int r = m0 + mt * 16 + (lane >> 2);
#pragma unroll
            for (int nf = 0; nf < 8; ++nf) {
                int c = n0 + nf * 8 + 2 * (lane & 3);
                float2 g2 = __ldg((const float2*)(gamma + c));
                float2 e2 = __ldg((const float2*)(beta + c));
                float2 o1, o2;
                o1.x = (acc[mt][nf][0] - mu[mt][0]) * rs[mt][0] * g2.x + e2.x;
                o1.y = (acc[mt][nf][1] - mu[mt][0]) * rs[mt][0] * g2.y + e2.y;
                o2.x = (acc[mt][nf][2] - mu[mt][1]) * rs[mt][1] * g2.x + e2.x;
                o2.y = (acc[mt][nf][3] - mu[mt][1]) * rs[mt][1] * g2.y + e2.y;
                *(float2*)(outp + tbase + (size_t)r * 128 + c) = o1;
                *(float2*)(outp + tbase + (size_t)(r + 8) * 128 + c) = o2;
            }
        }
    }
}

extern "C" void kernel_launch(void* const* d_in, const int* in_sizes, int n_in,
                              void* d_out, int out_size) {
    const float* inputs = (const float*)d_in[0];
    const float* Wq = (const float*)d_in[1];
    const float* bq = (const float*)d_in[2];
    const float* Wk = (const float*)d_in[3];
    const float* bk = (const float*)d_in[4];
    const float* Wv = (const float*)d_in[5];
    const float* bv = (const float*)d_in[6];
    const float* Wo = (const float*)d_in[7];
    const float* bo = (const float*)d_in[8];
    const float* gamma = (const float*)d_in[9];
    const float* beta  = (const float*)d_in[10];
    float* outp = (float*)d_out;

    prep_split<<<128, 256>>>(Wq, Wk, Wv, Wo);

    int grid = in_sizes[0] / 16384;   // 128 rows * 128 cols per CTA
    cudaFuncSetAttribute(fused_attn_fa,
                         cudaFuncAttributeMaxDynamicSharedMemorySize, SMEM_BYTES);
    fused_attn_fa<<<grid, NT, SMEM_BYTES>>>(inputs, bq, bk, bv, bo, gamma, beta, outp);
}

// round 17
// speedup vs baseline: 1.2215x; 1.2215x over previous
#include <cuda_runtime.h>
#include <cuda_fp16.h>
#include <cstdint>

// Fused SelfAttention, tensor-core HMMA (mma.sync f16, fp32 accum), 1-term fp16.
// E=128, S=32, H=4, D=32. CTA = 64 rows (2 batches), 256 threads, grid 8192.
// Warp w -> tile (m0=(w>>2)*32, n0=(w&3)*32) == attention block (batch, head).
// R16 = R14 body (32x32 warp tiles, register-resident attention) with weight
// fills converted to cp.async.cg and overlapped with register-only phases
// (q repack / softmax / ctx). Math identical to R14.
//
// SMEM:
//   A @0     : fp16 [64][128], 256B rows, 16B-chunk xor swizzle.  16KB
//   W @16384 : fp16 [128][128], 256B rows, swizzled weight image. 32KB
//   LN partials @49152 : float2[64][4].                            2KB

typedef unsigned int u32;

#define NT 256
#define AOFF 0
#define WOFF 16384
#define POFF 49152
#define SMEM_BYTES 51200
#define QSCALE 0.17677669529663687f

// 4 weights x 32KB swizzled fp16 image
__device__ __align__(16) unsigned char g_Wpk[131072];

// ---------------- prep: W -> fp16 swizzled smem images ----------------
__global__ void prep_split(const float* __restrict__ Wq, const float* __restrict__ Wk,
                           const float* __restrict__ Wv, const float* __restrict__ Wo) {
    int id = blockIdx.x * blockDim.x + threadIdx.x;   // 0..32767 u32 words
    const float* W = (id < 8192) ? Wq : (id < 16384) ? Wk : (id < 24576) ? Wv : Wo;
    int rem = id & 8191;
    int f = rem >> 6;          // row 0..127 (64 u32 words per 256B row)
    int w = rem & 63;
    int pc = w >> 2, j = w & 3;
    int lc = pc ^ (f & 7);
    int k0 = lc * 8 + j * 2;
    __half2 p = __halves2half2(__float2half_rn(W[f * 128 + k0]),
                               __float2half_rn(W[f * 128 + k0 + 1]));
    ((u32*)g_Wpk)[id] = *(u32*)&p;
}

// ---------------- helpers ----------------
__device__ __forceinline__ u32 s2u(const void* p) {
    u32 a;
    asm("{ .reg .u64 t; cvta.to.shared.u64 t, %1; cvt.u32.u64 %0, t; }" : "=r"(a) : "l"(p));
    return a;
}
__device__ __forceinline__ void ldsm4(u32* r, u32 a) {
    asm volatile("ldmatrix.sync.aligned.m8n8.x4.shared.b16 {%0,%1,%2,%3}, [%4];"
                 : "=r"(r[0]), "=r"(r[1]), "=r"(r[2]), "=r"(r[3]) : "r"(a));
}
__device__ __forceinline__ u32 movm_t(u32 s) {
    u32 d;
    asm("movmatrix.sync.aligned.m8n8.trans.b16 %0, %1;" : "=r"(d) : "r"(s));
    return d;
}
__device__ __forceinline__ void mma16816(float* c, const u32* a, u32 b0, u32 b1) {
    asm volatile(
        "mma.sync.aligned.m16n8k16.row.col.f32.f16.f16.f32 "
        "{%0,%1,%2,%3}, {%4,%5,%6,%7}, {%8,%9}, {%0,%1,%2,%3};"
        : "+f"(c[0]), "+f"(c[1]), "+f"(c[2]), "+f"(c[3])
        : "r"(a[0]), "r"(a[1]), "r"(a[2]), "r"(a[3]), "r"(b0), "r"(b1));
}
__device__ __forceinline__ u32 pkhf(float a, float b) {
    __half2 t = __halves2half2(__float2half_rn(a), __float2half_rn(b));
    return *(u32*)&t;
}
__device__ __forceinline__ void cpa16(u32 dst, const void* src) {
    asm volatile("cp.async.cg.shared.global [%0], [%1], 16;" :: "r"(dst), "l"(src));
}
__device__ __forceinline__ void cpa_commit() {
    asm volatile("cp.async.commit_group;" ::: "memory");
}
__device__ __forceinline__ void cpa_wait0() {
    asm volatile("cp.async.wait_group 0;" ::: "memory");
}

// issue async copy of weight image g into W buffer (no wait)
__device__ __forceinline__ void fillW_async(u32 smW, int g, int tid) {
    const char* src = (const char*)g_Wpk + g * 32768;
#pragma unroll
    for (int p = 0; p < 8; ++p) {
        int off = (p * NT + tid) * 16;
        cpa16(smW + off, src + off);
    }
    cpa_commit();
}

// C[m0:+32][n0:+32] = A(64x128 fp16) @ W^T(128x128 fp16), 1-term.
__device__ __forceinline__ void gemm32(u32 smA, u32 smW, int m0, int n0, int lane,
                                       float acc[2][4][4]) {
    u32 aRow[2]; int asw[2];
#pragma unroll
    for (int mt = 0; mt < 2; ++mt) {
        int ar = m0 + mt * 16 + (lane & 7) + ((lane & 8) ? 8 : 0);
        aRow[mt] = smA + ar * 256; asw[mt] = ar & 7;
    }
    const int acs = lane >> 4;
    u32 bRow[2]; int bsw[2];
#pragma unroll
    for (int ng = 0; ng < 2; ++ng) {
        int br = n0 + ng * 16 + (lane & 7) + ((lane & 16) ? 8 : 0);
        bRow[ng] = smW + br * 256; bsw[ng] = br & 7;
    }
    const int bcs = (lane >> 3) & 1;
#pragma unroll
    for (int mt = 0; mt < 2; ++mt)
#pragma unroll
        for (int nf = 0; nf < 4; ++nf)
#pragma unroll
            for (int c = 0; c < 4; ++c) acc[mt][nf][c] = 0.f;

#pragma unroll
    for (int j = 0; j < 8; ++j) {
        const int ach = 2 * j + acs, bch = 2 * j + bcs;
        u32 ah[2][4], bh[2][4];
#pragma unroll
        for (int mt = 0; mt < 2; ++mt)
            ldsm4(ah[mt], aRow[mt] + ((ach ^ asw[mt]) << 4));
#pragma unroll
        for (int ng = 0; ng < 2; ++ng)
            ldsm4(bh[ng], bRow[ng] + ((bch ^ bsw[ng]) << 4));
#pragma unroll
        for (int mt = 0; mt < 2; ++mt)
#pragma unroll
            for (int ng = 0; ng < 2; ++ng) {
                mma16816(acc[mt][2 * ng],     ah[mt], bh[ng][0], bh[ng][1]);
                mma16816(acc[mt][2 * ng + 1], ah[mt], bh[ng][2], bh[ng][3]);
            }
    }
}

// c-frags -> fp16 into the A-style [64][128] image (ctx writeback).
__device__ __forceinline__ void store_ctx(char* dst, const float acc[2][4][4],
                                          int m0, int n0, int lane) {
#pragma unroll
    for (int mt = 0; mt < 2; ++mt) {
        int r = m0 + mt * 16 + (lane >> 2);
        char* row0 = dst + r * 256;
        char* row1 = dst + (r + 8) * 256;
        int sw = r & 7;
#pragma unroll
        for (int nf = 0; nf < 4; ++nf) {
            int c = n0 + nf * 8 + 2 * (lane & 3);
            u32 h01 = pkhf(acc[mt][nf][0], acc[mt][nf][1]);
            u32 h23 = pkhf(acc[mt][nf][2], acc[mt][nf][3]);
            int ch = c >> 3, bo_ = (c & 7) * 2;
            *(u32*)(row0 + ((ch ^ sw) << 4) + bo_) = h01;
            *(u32*)(row1 + ((ch ^ sw) << 4) + bo_) = h23;
        }
    }
}

// ---------------- main kernel ----------------
__global__ void __launch_bounds__(NT, 2)
fused_attn_fa(const float* __restrict__ inputs,
              const float* __restrict__ bq, const float* __restrict__ bk,
              const float* __restrict__ bv, const float* __restrict__ bo,
              const float* __restrict__ gamma, const float* __restrict__ beta,
              float* __restrict__ outp)
{
    extern __shared__ char sm[];
    const int tid = threadIdx.x;
    const int lane = tid & 31;
    const int warp = tid >> 5;
    const u32 smb = s2u(sm);
    const u32 smA = smb + AOFF, smW = smb + WOFF;
    const int m0 = (warp >> 2) * 32;    // batch block (rows): 0 or 32
    const int n0 = (warp & 3) * 32;     // head block (cols)
    const int h = warp & 3;
    const size_t tbase = (size_t)blockIdx.x * 8192;

    // ---- async Wq fill, then A fill (x -> fp16) ----
    fillW_async(smW, 0, tid);
    {
        const float4* gx = (const float4*)(inputs + tbase);
#pragma unroll
        for (int p = 0; p < 8; ++p) {
            int e = p * NT + tid;
            int row = e >> 5, c4 = e & 31;
            float4 v = __ldg(gx + e);
            uint2 hi = make_uint2(pkhf(v.x, v.y), pkhf(v.z, v.w));
            char* arow = sm + AOFF + row * 256;
            int ch = c4 >> 1, off8 = (c4 & 1) * 8, sw = row & 7;
            *(uint2*)(arow + ((ch ^ sw) << 4) + off8) = hi;
        }
    }
    cpa_wait0();
    __syncthreads();

    float acc[2][4][4];

    // ======== Q gemm ========
    gemm32(smA, smW, m0, n0, lane, acc);
    __syncthreads();          // all warps done reading Wq
    fillW_async(smW, 1, tid); // Wk in flight...

    // ...overlapped with q repack (registers + bias LDG only)
    u32 qh[2][2][4];
#pragma unroll
    for (int mt = 0; mt < 2; ++mt)
#pragma unroll
        for (int nf = 0; nf < 4; ++nf) {
            int c = n0 + nf * 8 + 2 * (lane & 3);
            float2 b2 = __ldg((const float2*)(bq + c));
            float q0 = (acc[mt][nf][0] + b2.x) * QSCALE;
            float q1 = (acc[mt][nf][1] + b2.y) * QSCALE;
            float q2 = (acc[mt][nf][2] + b2.x) * QSCALE;
            float q3 = (acc[mt][nf][3] + b2.y) * QSCALE;
            int ks = nf >> 1, o = (nf & 1) * 2;
            qh[mt][ks][o] = pkhf(q0, q1);
            qh[mt][ks][o + 1] = pkhf(q2, q3);
        }
    cpa_wait0();
    __syncthreads();          // Wk ready

    // ======== K gemm ========
    gemm32(smA, smW, m0, n0, lane, acc);
    __syncthreads();          // done reading Wk
    fillW_async(smW, 2, tid); // Wv in flight...

    // ...overlapped with k repack + scores + softmax + p repack (register-only)
    u32 kbh[2][2][4];
#pragma unroll
    for (int mt = 0; mt < 2; ++mt)
#pragma unroll
        for (int nf = 0; nf < 4; ++nf) {
            int c = n0 + nf * 8 + 2 * (lane & 3);
            float2 b2 = __ldg((const float2*)(bk + c));
            kbh[mt][0][nf] = pkhf(acc[mt][nf][0] + b2.x, acc[mt][nf][1] + b2.y);
            kbh[mt][1][nf] = pkhf(acc[mt][nf][2] + b2.x, acc[mt][nf][3] + b2.y);
        }

    float S[2][4][4];
#pragma unroll
    for (int mt = 0; mt < 2; ++mt)
#pragma unroll
        for (int nf = 0; nf < 4; ++nf)
#pragma unroll
            for (int c = 0; c < 4; ++c) S[mt][nf][c] = 0.f;
#pragma unroll
    for (int ks = 0; ks < 2; ++ks)
#pragma unroll
        for (int ms = 0; ms < 2; ++ms)
#pragma unroll
            for (int mk = 0; mk < 2; ++mk)
#pragma unroll
                for (int tb = 0; tb < 2; ++tb)
                    mma16816(S[ms][2 * mk + tb], qh[ms][ks],
                             kbh[mk][tb][2 * ks], kbh[mk][tb][2 * ks + 1]);

    u32 ph[2][2][4];
    {
        float mx[2][2], iv[2][2];
#pragma unroll
        for (int mt = 0; mt < 2; ++mt)
#pragma unroll
            for (int hf = 0; hf < 2; ++hf) {
                float m = -1e30f;
#pragma unroll
                for (int nf = 0; nf < 4; ++nf)
                    m = fmaxf(m, fmaxf(S[mt][nf][hf * 2], S[mt][nf][hf * 2 + 1]));
                m = fmaxf(m, __shfl_xor_sync(~0u, m, 1));
                m = fmaxf(m, __shfl_xor_sync(~0u, m, 2));
                mx[mt][hf] = m;
            }
#pragma unroll
        for (int mt = 0; mt < 2; ++mt)
#pragma unroll
            for (int nf = 0; nf < 4; ++nf) {
                S[mt][nf][0] = __expf(S[mt][nf][0] - mx[mt][0]);
                S[mt][nf][1] = __expf(S[mt][nf][1] - mx[mt][0]);
                S[mt][nf][2] = __expf(S[mt][nf][2] - mx[mt][1]);
                S[mt][nf][3] = __expf(S[mt][nf][3] - mx[mt][1]);
            }
#pragma unroll
        for (int mt = 0; mt < 2; ++mt)
#pragma unroll
            for (int hf = 0; hf < 2; ++hf) {
                float s = 0.f;
#pragma unroll
                for (int nf = 0; nf < 4; ++nf)
                    s += S[mt][nf][hf * 2] + S[mt][nf][hf * 2 + 1];
                s += __shfl_xor_sync(~0u, s, 1);
                s += __shfl_xor_sync(~0u, s, 2);
                iv[mt][hf] = 1.f / s;
            }
#pragma unroll
        for (int mt = 0; mt < 2; ++mt)
#pragma unroll
            for (int nf = 0; nf < 4; ++nf) {
                float p0 = S[mt][nf][0] * iv[mt][0];
                float p1 = S[mt][nf][1] * iv[mt][0];
                float p2 = S[mt][nf][2] * iv[mt][1];
                float p3 = S[mt][nf][3] * iv[mt][1];
                int ks = nf >> 1, o = (nf & 1) * 2;
                ph[mt][ks][o] = pkhf(p0, p1);
                ph[mt][ks][o + 1] = pkhf(p2, p3);
            }
    }
    cpa_wait0();
    __syncthreads();          // Wv ready

    // ======== V gemm ========
    gemm32(smA, smW, m0, n0, lane, acc);
    __syncthreads();          // done reading Wv AND A (A now rewritable)
    fillW_async(smW, 3, tid); // Wo in flight...

    // ...overlapped with v repack + ctx MMAs + ctx store
    u32 vbh[2][2][4];
#pragma unroll
    for (int mt = 0; mt < 2; ++mt)
#pragma unroll
        for (int nf = 0; nf < 4; ++nf) {
            int c = n0 + nf * 8 + 2 * (lane & 3);
            float2 b2 = __ldg((const float2*)(bv + c));
            u32 h01 = pkhf(acc[mt][nf][0] + b2.x, acc[mt][nf][1] + b2.y);
            u32 h23 = pkhf(acc[mt][nf][2] + b2.x, acc[mt][nf][3] + b2.y);
            vbh[mt][0][nf] = movm_t(h01);
            vbh[mt][1][nf] = movm_t(h23);
        }

    float C[2][4][4];
#pragma unroll
    for (int mt = 0; mt < 2; ++mt)
#pragma unroll
        for (int nf = 0; nf < 4; ++nf)
#pragma unroll
            for (int c = 0; c < 4; ++c) C[mt][nf][c] = 0.f;
#pragma unroll
    for (int kt = 0; kt < 2; ++kt)
#pragma unroll
        for (int ms = 0; ms < 2; ++ms)
#pragma unroll
            for (int nf = 0; nf < 4; ++nf)
                mma16816(C[ms][nf], ph[ms][kt], vbh[kt][0][nf], vbh[kt][1][nf]);

    store_ctx(sm + AOFF, C, m0, n0, lane);     // ctx -> A tile (fp16)
    cpa_wait0();
    __syncthreads();          // Wo ready + ctx visible

    // ======== out projection + epilogue ========
    gemm32(smA, smW, m0, n0, lane, acc);

    {
        float s1[2][2] = {{0.f, 0.f}, {0.f, 0.f}};
        float s2[2][2] = {{0.f, 0.f}, {0.f, 0.f}};
#pragma unroll
        for (int mt = 0; mt < 2; ++mt) {
            int r = m0 + mt * 16 + (lane >> 2);
#pragma unroll
            for (int nf = 0; nf < 4; ++nf) {
                int c = n0 + nf * 8 + 2 * (lane & 3);
                float2 b2 = __ldg((const float2*)(bo + c));
                float2 xa = __ldg((const float2*)(inputs + tbase + (size_t)r * 128 + c));
                float2 xb = __ldg((const float2*)(inputs + tbase + (size_t)(r + 8) * 128 + c));
                acc[mt][nf][0] += b2.x + xa.x; acc[mt][nf][1] += b2.y + xa.y;
                acc[mt][nf][2] += b2.x + xb.x; acc[mt][nf][3] += b2.y + xb.y;
                s1[mt][0] += acc[mt][nf][0] + acc[mt][nf][1];
                s2[mt][0] += acc[mt][nf][0] * acc[mt][nf][0] + acc[mt][nf][1] * acc[mt][nf][1];
                s1[mt][1] += acc[mt][nf][2] + acc[mt][nf][3];
                s2[mt][1] += acc[mt][nf][2] * acc[mt][nf][2] + acc[mt][nf][3] * acc[mt][nf][3];
            }
        }
#pragma unroll
        for (int mt = 0; mt < 2; ++mt)
#pragma unroll
            for (int hf = 0; hf < 2; ++hf) {
                s1[mt][hf] += __shfl_xor_sync(~0u, s1[mt][hf], 1);
                s1[mt][hf] += __shfl_xor_sync(~0u, s1[mt][hf], 2);
                s2[mt][hf] += __shfl_xor_sync(~0u, s2[mt][hf], 1);
                s2[mt][hf] += __shfl_xor_sync(~0u, s2[mt][hf], 2);
            }
        float2* part = (float2*)(sm + POFF);
        if ((lane & 3) == 0) {
#pragma unroll
            for (int mt = 0; mt < 2; ++mt) {
                int r = m0 + mt * 16 + (lane >> 2);
                part[r * 4 + h] = make_float2(s1[mt][0], s2[mt][0]);
                part[(r + 8) * 4 + h] = make_float2(s1[mt][1], s2[mt][1]);
            }
        }
        __syncthreads();
        float mu[2][2], rs[2][2];
#pragma unroll
        for (int mt = 0; mt < 2; ++mt)
#pragma unroll
            for (int hf = 0; hf < 2; ++hf) {
                int r = m0 + mt * 16 + (lane >> 2) + hf * 8;
                float2 p0 = part[r * 4 + 0], p1 = part[r * 4 + 1];
                float2 p2 = part[r * 4 + 2], p3 = part[r * 4 + 3];
                float S1 = p0.x + p1.x + p2.x + p3.x;
                float S2 = p0.y + p1.y + p2.y + p3.y;
                float m = S1 * (1.f / 128.f);
                float v = S2 * (1.f / 128.f) - m * m;
                mu[mt][hf] = m;
                rs[mt][hf] = rsqrtf(v + 1e-5f);
            }
#pragma unroll
        for (int mt = 0; mt < 2; ++mt) {
            int r = m0 + mt * 16 + (lane >> 2);
#pragma unroll
            for (int nf = 0; nf < 4; ++nf) {
                int c = n0 + nf * 8 + 2 * (lane & 3);
                float2 g2 = __ldg((const float2*)(gamma + c));
                float2 e2 = __ldg((const float2*)(beta + c));
                float2 o1, o2;
                o1.x = (acc[mt][nf][0] - mu[mt][0]) * rs[mt][0] * g2.x + e2.x;
                o1.y = (acc[mt][nf][1] - mu[mt][0]) * rs[mt][0] * g2.y + e2.y;
                o2.x = (acc[mt][nf][2] - mu[mt][1]) * rs[mt][1] * g2.x + e2.x;
                o2.y = (acc[mt][nf][3] - mu[mt][1]) * rs[mt][1] * g2.y + e2.y;
                *(float2*)(outp + tbase + (size_t)r * 128 + c) = o1;
                *(float2*)(outp + tbase + (size_t)(r + 8) * 128 + c) = o2;
            }
        }
    }
}

extern "C" void kernel_launch(void* const* d_in, const int* in_sizes, int n_in,
                              void* d_out, int out_size) {
    const float* inputs = (const float*)d_in[0];
    const float* Wq = (const float*)d_in[1];
    const float* bq = (const float*)d_in[2];
    const float* Wk = (const float*)d_in[3];
    const float* bk = (const float*)d_in[4];
    const float* Wv = (const float*)d_in[5];
    const float* bv = (const float*)d_in[6];
    const float* Wo = (const float*)d_in[7];
    const float* bo = (const float*)d_in[8];
    const float* gamma = (const float*)d_in[9];
    const float* beta  = (const float*)d_in[10];
    float* outp = (float*)d_out;

    prep_split<<<128, 256>>>(Wq, Wk, Wv, Wo);

    int grid = in_sizes[0] / 8192;   // 64 rows * 128 cols per CTA
    cudaFuncSetAttribute(fused_attn_fa,
                         cudaFuncAttributeMaxDynamicSharedMemorySize, SMEM_BYTES);
    fused_attn_fa<<<grid, NT, SMEM_BYTES>>>(inputs, bq, bk, bv, bo, gamma, beta, outp);
}